// round 1
// baseline (speedup 1.0000x reference)
#include <cuda_runtime.h>
#include <math.h>

#define S_LEN 4096
#define D_MODEL 768
#define N_HEADS 12
#define D_HEAD 64

// ---------------- scratch (no allocations allowed) ----------------
__device__ float g_Q[S_LEN * D_MODEL];
__device__ float g_K[S_LEN * D_MODEL];
__device__ float g_V[S_LEN * D_MODEL];
__device__ float g_CTX[S_LEN * D_MODEL];

// ---------------- SGEMM: C[M,N] = (A[M,K] @ B[N,K]^T + bias[N]) * scale ----
// BM=BN=128, BK=8, TM=TN=8, 256 threads.
#define BM 128
#define BN 128
#define BK 8
#define TM 8
#define TN 8

__global__ __launch_bounds__(256)
void sgemm_nt_bias(const float* __restrict__ A, const float* __restrict__ B,
                   const float* __restrict__ bias, float* __restrict__ C,
                   int M, int N, int K, float scale) {
    __shared__ float As[BK][BM];
    __shared__ float Bs[BK][BN];

    const int tid = threadIdx.x;
    const int crow = blockIdx.y * BM;
    const int ccol = blockIdx.x * BN;

    const int ldRow  = tid >> 1;        // 0..127
    const int ldCol4 = (tid & 1) * 4;   // 0 or 4

    const int ty = tid >> 4;            // 0..15
    const int tx = tid & 15;            // 0..15

    float acc[TM][TN];
    #pragma unroll
    for (int i = 0; i < TM; i++)
        #pragma unroll
        for (int j = 0; j < TN; j++) acc[i][j] = 0.f;

    for (int kt = 0; kt < K; kt += BK) {
        // load A tile (transposed store)
        float4 a4 = *reinterpret_cast<const float4*>(&A[(crow + ldRow) * K + kt + ldCol4]);
        As[ldCol4 + 0][ldRow] = a4.x;
        As[ldCol4 + 1][ldRow] = a4.y;
        As[ldCol4 + 2][ldRow] = a4.z;
        As[ldCol4 + 3][ldRow] = a4.w;
        // load B tile (transposed store)
        float4 b4 = *reinterpret_cast<const float4*>(&B[(ccol + ldRow) * K + kt + ldCol4]);
        Bs[ldCol4 + 0][ldRow] = b4.x;
        Bs[ldCol4 + 1][ldRow] = b4.y;
        Bs[ldCol4 + 2][ldRow] = b4.z;
        Bs[ldCol4 + 3][ldRow] = b4.w;
        __syncthreads();

        #pragma unroll
        for (int k = 0; k < BK; k++) {
            float ra[TM], rb[TN];
            *reinterpret_cast<float4*>(&ra[0]) = *reinterpret_cast<const float4*>(&As[k][ty * TM + 0]);
            *reinterpret_cast<float4*>(&ra[4]) = *reinterpret_cast<const float4*>(&As[k][ty * TM + 4]);
            *reinterpret_cast<float4*>(&rb[0]) = *reinterpret_cast<const float4*>(&Bs[k][tx * TN + 0]);
            *reinterpret_cast<float4*>(&rb[4]) = *reinterpret_cast<const float4*>(&Bs[k][tx * TN + 4]);
            #pragma unroll
            for (int i = 0; i < TM; i++)
                #pragma unroll
                for (int j = 0; j < TN; j++)
                    acc[i][j] = fmaf(ra[i], rb[j], acc[i][j]);
        }
        __syncthreads();
    }

    // epilogue: bias + scale, float4 stores
    #pragma unroll
    for (int i = 0; i < TM; i++) {
        int row = crow + ty * TM + i;
        #pragma unroll
        for (int j = 0; j < TN; j += 4) {
            int col = ccol + tx * TN + j;
            float4 bv = *reinterpret_cast<const float4*>(&bias[col]);
            float4 out;
            out.x = (acc[i][j + 0] + bv.x) * scale;
            out.y = (acc[i][j + 1] + bv.y) * scale;
            out.z = (acc[i][j + 2] + bv.z) * scale;
            out.w = (acc[i][j + 3] + bv.w) * scale;
            *reinterpret_cast<float4*>(&C[row * N + col]) = out;
        }
    }
}

// ---------------- Flash attention (fp32) ----------------
// grid: (S/BQ, H). 128 threads, one query row per thread.
// Q row + O accumulator in registers; K/V 64-key tiles in smem (broadcast reads).
#define BQ 128
#define TKEYS 64

__global__ __launch_bounds__(128)
void flash_attn(const float* __restrict__ Q, const float* __restrict__ K,
                const float* __restrict__ V, const int* __restrict__ mask,
                float* __restrict__ Ctx) {
    __shared__ float Ksh[TKEYS][D_HEAD];
    __shared__ float Vsh[TKEYS][D_HEAD];
    __shared__ float msk[TKEYS];

    const int h = blockIdx.y;
    const int q0 = blockIdx.x * BQ;
    const int r = threadIdx.x;   // query row within tile

    float q[D_HEAD];
    float o[D_HEAD];
    #pragma unroll
    for (int i = 0; i < D_HEAD; i++) o[i] = 0.f;

    const float* qp = Q + (size_t)(q0 + r) * D_MODEL + h * D_HEAD;
    #pragma unroll
    for (int i = 0; i < D_HEAD / 4; i++)
        *reinterpret_cast<float4*>(&q[i * 4]) = *reinterpret_cast<const float4*>(&qp[i * 4]);

    float m = -1e30f, l = 0.f;

    for (int kt = 0; kt < S_LEN; kt += TKEYS) {
        __syncthreads();
        // load K/V tiles (coalesced float4)
        for (int t = threadIdx.x; t < TKEYS * (D_HEAD / 4); t += BQ) {
            int row = t / (D_HEAD / 4);
            int c = t % (D_HEAD / 4);
            const float4* kp = reinterpret_cast<const float4*>(K + (size_t)(kt + row) * D_MODEL + h * D_HEAD);
            const float4* vp = reinterpret_cast<const float4*>(V + (size_t)(kt + row) * D_MODEL + h * D_HEAD);
            reinterpret_cast<float4*>(Ksh[row])[c] = kp[c];
            reinterpret_cast<float4*>(Vsh[row])[c] = vp[c];
        }
        for (int t = threadIdx.x; t < TKEYS; t += BQ)
            msk[t] = (mask[kt + t] != 0) ? 0.f : -1e30f;
        __syncthreads();

        #pragma unroll 1
        for (int jc = 0; jc < TKEYS; jc += 16) {
            float s[16];
            #pragma unroll
            for (int j = 0; j < 16; j++) {
                float acc = 0.f;
                #pragma unroll
                for (int d = 0; d < D_HEAD; d++)
                    acc = fmaf(q[d], Ksh[jc + j][d], acc);
                s[j] = acc + msk[jc + j];
            }
            float mc = s[0];
            #pragma unroll
            for (int j = 1; j < 16; j++) mc = fmaxf(mc, s[j]);
            float mnew = fmaxf(m, mc);
            float corr = __expf(m - mnew);
            m = mnew;
            l *= corr;
            #pragma unroll
            for (int d = 0; d < D_HEAD; d++) o[d] *= corr;
            #pragma unroll
            for (int j = 0; j < 16; j++) {
                float p = __expf(s[j] - mnew);
                l += p;
                #pragma unroll
                for (int d = 0; d < D_HEAD; d++)
                    o[d] = fmaf(p, Vsh[jc + j][d], o[d]);
            }
        }
    }

    float inv = 1.f / l;
    float* op = Ctx + (size_t)(q0 + r) * D_MODEL + h * D_HEAD;
    #pragma unroll
    for (int i = 0; i < D_HEAD / 4; i++) {
        float4 v;
        v.x = o[i * 4 + 0] * inv;
        v.y = o[i * 4 + 1] * inv;
        v.z = o[i * 4 + 2] * inv;
        v.w = o[i * 4 + 3] * inv;
        *reinterpret_cast<float4*>(&op[i * 4]) = v;
    }
}

// ---------------- launch ----------------
extern "C" void kernel_launch(void* const* d_in, const int* in_sizes, int n_in,
                              void* d_out, int out_size) {
    const float* query = (const float*)d_in[0];
    const float* key   = (const float*)d_in[1];
    const float* value = (const float*)d_in[2];
    const int*   mask  = (const int*)d_in[3];
    const float* Wq = (const float*)d_in[4];
    const float* bq = (const float*)d_in[5];
    const float* Wk = (const float*)d_in[6];
    const float* bk = (const float*)d_in[7];
    const float* Wv = (const float*)d_in[8];
    const float* bv = (const float*)d_in[9];
    const float* Wo = (const float*)d_in[10];
    const float* bo = (const float*)d_in[11];
    float* out = (float*)d_out;

    void *pQ, *pK, *pV, *pC;
    cudaGetSymbolAddress(&pQ, g_Q);
    cudaGetSymbolAddress(&pK, g_K);
    cudaGetSymbolAddress(&pV, g_V);
    cudaGetSymbolAddress(&pC, g_CTX);

    dim3 gridP(D_MODEL / BN, S_LEN / BM);   // (6, 32)
    const float qscale = 1.0f / 8.0f;       // 1/sqrt(64)

    sgemm_nt_bias<<<gridP, 256>>>(query, Wq, bq, (float*)pQ, S_LEN, D_MODEL, D_MODEL, qscale);
    sgemm_nt_bias<<<gridP, 256>>>(key,   Wk, bk, (float*)pK, S_LEN, D_MODEL, D_MODEL, 1.0f);
    sgemm_nt_bias<<<gridP, 256>>>(value, Wv, bv, (float*)pV, S_LEN, D_MODEL, D_MODEL, 1.0f);

    dim3 gridA(S_LEN / BQ, N_HEADS);        // (32, 12)
    flash_attn<<<gridA, BQ>>>((const float*)pQ, (const float*)pK, (const float*)pV, mask, (float*)pC);

    sgemm_nt_bias<<<gridP, 256>>>((const float*)pC, Wo, bo, out, S_LEN, D_MODEL, D_MODEL, 1.0f);
}

// round 2
// speedup vs baseline: 5.2500x; 5.2500x over previous
#include <cuda_runtime.h>
#include <math.h>

#define S_LEN 4096
#define D_MODEL 768
#define N_HEADS 12
#define D_HEAD 64

// ---------------- scratch (no allocations allowed) ----------------
__device__ float g_Q[S_LEN * D_MODEL];
__device__ float g_K[S_LEN * D_MODEL];
__device__ float g_V[S_LEN * D_MODEL];
__device__ float g_CTX[S_LEN * D_MODEL];

// ---------------- tf32 helpers ----------------
__device__ __forceinline__ unsigned cvt_tf32(float f) {
    unsigned r;
    asm("cvt.rna.tf32.f32 %0, %1;" : "=r"(r) : "f"(f));
    return r;
}
__device__ __forceinline__ float cvt_tf32f(float f) {
    return __uint_as_float(cvt_tf32(f));
}
__device__ __forceinline__ void mma_tf32(float* c, const unsigned* a, unsigned b0, unsigned b1) {
    asm volatile(
        "mma.sync.aligned.m16n8k8.row.col.f32.tf32.tf32.f32 "
        "{%0,%1,%2,%3}, {%4,%5,%6,%7}, {%8,%9}, {%0,%1,%2,%3};\n"
        : "+f"(c[0]), "+f"(c[1]), "+f"(c[2]), "+f"(c[3])
        : "r"(a[0]), "r"(a[1]), "r"(a[2]), "r"(a[3]), "r"(b0), "r"(b1));
}

// ============================================================================
// GEMM (tf32 tensor core): C[M,N] = (A[M,K] @ B[N,K]^T + bias[N]) * scale
// Block: 128 threads (4 warps), tile BM=64 (warp m = 16 rows), BN=64, BK=32.
// ============================================================================
#define GBM 64
#define GBN 64
#define GBK 32
#define GAS 36   // Ash row stride (pad)
#define GBS 36   // Bsh row stride (pad)

__global__ __launch_bounds__(128)
void gemm_tf32(const float* __restrict__ A, const float* __restrict__ B,
               const float* __restrict__ bias, float* __restrict__ C,
               int M, int N, int K, float scale) {
    __shared__ float Ash[GBM * GAS];
    __shared__ float Bsh[GBN * GBS];

    const int tid  = threadIdx.x;
    const int warp = tid >> 5;
    const int lane = tid & 31;
    const int lr = lane >> 2;   // 0..7
    const int lc = lane & 3;    // 0..3

    const int crow = blockIdx.y * GBM;
    const int ccol = blockIdx.x * GBN;

    float acc[8][4];
    #pragma unroll
    for (int nc = 0; nc < 8; nc++)
        #pragma unroll
        for (int i = 0; i < 4; i++) acc[nc][i] = 0.f;

    for (int kt = 0; kt < K; kt += GBK) {
        // load A tile (64 x 32) and B tile (64 x 32), tf32-rounded
        #pragma unroll
        for (int it = 0; it < 4; it++) {
            int t = tid + it * 128;              // 0..511
            int row = t >> 3;                     // 0..63
            int c4  = (t & 7) * 4;                // 0..28
            float4 a4 = *reinterpret_cast<const float4*>(&A[(size_t)(crow + row) * K + kt + c4]);
            Ash[row * GAS + c4 + 0] = cvt_tf32f(a4.x);
            Ash[row * GAS + c4 + 1] = cvt_tf32f(a4.y);
            Ash[row * GAS + c4 + 2] = cvt_tf32f(a4.z);
            Ash[row * GAS + c4 + 3] = cvt_tf32f(a4.w);
            float4 b4 = *reinterpret_cast<const float4*>(&B[(size_t)(ccol + row) * K + kt + c4]);
            Bsh[row * GBS + c4 + 0] = cvt_tf32f(b4.x);
            Bsh[row * GBS + c4 + 1] = cvt_tf32f(b4.y);
            Bsh[row * GBS + c4 + 2] = cvt_tf32f(b4.z);
            Bsh[row * GBS + c4 + 3] = cvt_tf32f(b4.w);
        }
        __syncthreads();

        #pragma unroll
        for (int kc = 0; kc < GBK / 8; kc++) {
            unsigned a[4];
            a[0] = __float_as_uint(Ash[(warp * 16 + lr    ) * GAS + kc * 8 + lc    ]);
            a[1] = __float_as_uint(Ash[(warp * 16 + lr + 8) * GAS + kc * 8 + lc    ]);
            a[2] = __float_as_uint(Ash[(warp * 16 + lr    ) * GAS + kc * 8 + lc + 4]);
            a[3] = __float_as_uint(Ash[(warp * 16 + lr + 8) * GAS + kc * 8 + lc + 4]);
            #pragma unroll
            for (int nc = 0; nc < 8; nc++) {
                unsigned b0 = __float_as_uint(Bsh[(nc * 8 + lr) * GBS + kc * 8 + lc    ]);
                unsigned b1 = __float_as_uint(Bsh[(nc * 8 + lr) * GBS + kc * 8 + lc + 4]);
                mma_tf32(acc[nc], a, b0, b1);
            }
        }
        __syncthreads();
    }

    // epilogue: bias + scale
    int row0 = crow + warp * 16 + lr;
    #pragma unroll
    for (int nc = 0; nc < 8; nc++) {
        int col = ccol + nc * 8 + 2 * lc;
        float b0 = bias[col], b1 = bias[col + 1];
        float2 v0, v1;
        v0.x = (acc[nc][0] + b0) * scale;
        v0.y = (acc[nc][1] + b1) * scale;
        v1.x = (acc[nc][2] + b0) * scale;
        v1.y = (acc[nc][3] + b1) * scale;
        *reinterpret_cast<float2*>(&C[(size_t)row0 * N + col])       = v0;
        *reinterpret_cast<float2*>(&C[(size_t)(row0 + 8) * N + col]) = v1;
    }
}

// ============================================================================
// Flash attention, tf32 tensor core.
// Block: 128 threads (4 warps), each warp owns 16 query rows -> BQ=64.
// Key tiles of BK=64 staged in smem (tf32-rounded). grid = (S/64, H).
// ============================================================================
#define FBQ 64
#define FBK 64
#define KS 68    // Ksh row stride
#define VS 72    // Vsh row stride
#define PS 68    // Psh row stride

// dynamic smem: Ksh[64*KS] + Vsh[64*VS] + Psh[4*16*PS] + msk[64]
#define FSMEM_FLOATS (64 * KS + 64 * VS + 4 * 16 * PS + 64)

__global__ __launch_bounds__(128)
void flash_attn_mma(const float* __restrict__ Q, const float* __restrict__ K,
                    const float* __restrict__ V, const int* __restrict__ mask,
                    float* __restrict__ Ctx) {
    extern __shared__ float sm[];
    float* Ksh = sm;
    float* Vsh = Ksh + 64 * KS;
    float* Psh = Vsh + 64 * VS;
    float* msk = Psh + 4 * 16 * PS;

    const int h  = blockIdx.y;
    const int q0 = blockIdx.x * FBQ;
    const int tid  = threadIdx.x;
    const int warp = tid >> 5;
    const int lane = tid & 31;
    const int lr = lane >> 2;   // 0..7
    const int lc = lane & 3;    // 0..3

    float* Pw = Psh + warp * 16 * PS;

    // Q fragments for this warp's 16 rows (held in regs for whole kernel)
    unsigned aq[8][4];
    const float* Qb = Q + (size_t)(q0 + warp * 16) * D_MODEL + h * D_HEAD;
    #pragma unroll
    for (int kc = 0; kc < 8; kc++) {
        aq[kc][0] = cvt_tf32(Qb[(size_t)(lr    ) * D_MODEL + kc * 8 + lc    ]);
        aq[kc][1] = cvt_tf32(Qb[(size_t)(lr + 8) * D_MODEL + kc * 8 + lc    ]);
        aq[kc][2] = cvt_tf32(Qb[(size_t)(lr    ) * D_MODEL + kc * 8 + lc + 4]);
        aq[kc][3] = cvt_tf32(Qb[(size_t)(lr + 8) * D_MODEL + kc * 8 + lc + 4]);
    }

    float o[8][4];
    #pragma unroll
    for (int nc = 0; nc < 8; nc++)
        #pragma unroll
        for (int i = 0; i < 4; i++) o[nc][i] = 0.f;
    float m0 = -1e30f, m1 = -1e30f, l0 = 0.f, l1 = 0.f;

    for (int kt = 0; kt < S_LEN; kt += FBK) {
        __syncthreads();
        // stage K/V tiles (tf32-rounded), coalesced float4 reads
        #pragma unroll
        for (int it = 0; it < 8; it++) {
            int t = tid + it * 128;               // 0..1023
            int row = t >> 4;                      // 0..63
            int c4  = (t & 15) * 4;                // 0..60
            const float* kp = K + (size_t)(kt + row) * D_MODEL + h * D_HEAD + c4;
            const float* vp = V + (size_t)(kt + row) * D_MODEL + h * D_HEAD + c4;
            float4 k4 = *reinterpret_cast<const float4*>(kp);
            float4 v4 = *reinterpret_cast<const float4*>(vp);
            Ksh[row * KS + c4 + 0] = cvt_tf32f(k4.x);
            Ksh[row * KS + c4 + 1] = cvt_tf32f(k4.y);
            Ksh[row * KS + c4 + 2] = cvt_tf32f(k4.z);
            Ksh[row * KS + c4 + 3] = cvt_tf32f(k4.w);
            Vsh[row * VS + c4 + 0] = cvt_tf32f(v4.x);
            Vsh[row * VS + c4 + 1] = cvt_tf32f(v4.y);
            Vsh[row * VS + c4 + 2] = cvt_tf32f(v4.z);
            Vsh[row * VS + c4 + 3] = cvt_tf32f(v4.w);
        }
        if (tid < FBK) msk[tid] = (mask[kt + tid] != 0) ? 0.f : -1e30f;
        __syncthreads();

        // S = Q @ K^T  (16 x 64 per warp)
        float cs[8][4];
        #pragma unroll
        for (int nc = 0; nc < 8; nc++)
            #pragma unroll
            for (int i = 0; i < 4; i++) cs[nc][i] = 0.f;
        #pragma unroll
        for (int kc = 0; kc < 8; kc++) {
            #pragma unroll
            for (int nc = 0; nc < 8; nc++) {
                unsigned b0 = __float_as_uint(Ksh[(nc * 8 + lr) * KS + kc * 8 + lc    ]);
                unsigned b1 = __float_as_uint(Ksh[(nc * 8 + lr) * KS + kc * 8 + lc + 4]);
                mma_tf32(cs[nc], aq[kc], b0, b1);
            }
        }

        // mask add
        #pragma unroll
        for (int nc = 0; nc < 8; nc++) {
            float mk0 = msk[nc * 8 + 2 * lc];
            float mk1 = msk[nc * 8 + 2 * lc + 1];
            cs[nc][0] += mk0; cs[nc][1] += mk1;
            cs[nc][2] += mk0; cs[nc][3] += mk1;
        }

        // online softmax: row r = lane/4 (c0,c1), row r+8 (c2,c3)
        float mx0 = -1e30f, mx1 = -1e30f;
        #pragma unroll
        for (int nc = 0; nc < 8; nc++) {
            mx0 = fmaxf(mx0, fmaxf(cs[nc][0], cs[nc][1]));
            mx1 = fmaxf(mx1, fmaxf(cs[nc][2], cs[nc][3]));
        }
        mx0 = fmaxf(mx0, __shfl_xor_sync(0xffffffff, mx0, 1));
        mx0 = fmaxf(mx0, __shfl_xor_sync(0xffffffff, mx0, 2));
        mx1 = fmaxf(mx1, __shfl_xor_sync(0xffffffff, mx1, 1));
        mx1 = fmaxf(mx1, __shfl_xor_sync(0xffffffff, mx1, 2));

        float m0n = fmaxf(m0, mx0);
        float m1n = fmaxf(m1, mx1);
        float corr0 = __expf(m0 - m0n);
        float corr1 = __expf(m1 - m1n);
        m0 = m0n; m1 = m1n;
        l0 *= corr0; l1 *= corr1;
        #pragma unroll
        for (int nc = 0; nc < 8; nc++) {
            o[nc][0] *= corr0; o[nc][1] *= corr0;
            o[nc][2] *= corr1; o[nc][3] *= corr1;
        }

        // P = exp(S - m), accumulate l, store P (tf32) to smem
        #pragma unroll
        for (int nc = 0; nc < 8; nc++) {
            float p0 = __expf(cs[nc][0] - m0);
            float p1 = __expf(cs[nc][1] - m0);
            float p2 = __expf(cs[nc][2] - m1);
            float p3 = __expf(cs[nc][3] - m1);
            l0 += p0 + p1;
            l1 += p2 + p3;
            float2 w0; w0.x = cvt_tf32f(p0); w0.y = cvt_tf32f(p1);
            float2 w1; w1.x = cvt_tf32f(p2); w1.y = cvt_tf32f(p3);
            *reinterpret_cast<float2*>(&Pw[(lr    ) * PS + nc * 8 + 2 * lc]) = w0;
            *reinterpret_cast<float2*>(&Pw[(lr + 8) * PS + nc * 8 + 2 * lc]) = w1;
        }
        __syncwarp();

        // O += P @ V  (16 x 64 per warp), k = keys
        #pragma unroll
        for (int kc = 0; kc < 8; kc++) {
            unsigned a[4];
            a[0] = __float_as_uint(Pw[(lr    ) * PS + kc * 8 + lc    ]);
            a[1] = __float_as_uint(Pw[(lr + 8) * PS + kc * 8 + lc    ]);
            a[2] = __float_as_uint(Pw[(lr    ) * PS + kc * 8 + lc + 4]);
            a[3] = __float_as_uint(Pw[(lr + 8) * PS + kc * 8 + lc + 4]);
            #pragma unroll
            for (int nc = 0; nc < 8; nc++) {
                unsigned b0 = __float_as_uint(Vsh[(kc * 8 + lc    ) * VS + nc * 8 + lr]);
                unsigned b1 = __float_as_uint(Vsh[(kc * 8 + lc + 4) * VS + nc * 8 + lr]);
                mma_tf32(o[nc], a, b0, b1);
            }
        }
    }

    // finalize: reduce row sums across the 4 lanes of each row group
    l0 += __shfl_xor_sync(0xffffffff, l0, 1);
    l0 += __shfl_xor_sync(0xffffffff, l0, 2);
    l1 += __shfl_xor_sync(0xffffffff, l1, 1);
    l1 += __shfl_xor_sync(0xffffffff, l1, 2);
    float inv0 = 1.f / l0;
    float inv1 = 1.f / l1;

    float* O0 = Ctx + (size_t)(q0 + warp * 16 + lr) * D_MODEL + h * D_HEAD;
    float* O1 = O0 + (size_t)8 * D_MODEL;
    #pragma unroll
    for (int nc = 0; nc < 8; nc++) {
        int col = nc * 8 + 2 * lc;
        float2 v0; v0.x = o[nc][0] * inv0; v0.y = o[nc][1] * inv0;
        float2 v1; v1.x = o[nc][2] * inv1; v1.y = o[nc][3] * inv1;
        *reinterpret_cast<float2*>(&O0[col]) = v0;
        *reinterpret_cast<float2*>(&O1[col]) = v1;
    }
}

// ---------------- launch ----------------
extern "C" void kernel_launch(void* const* d_in, const int* in_sizes, int n_in,
                              void* d_out, int out_size) {
    const float* query = (const float*)d_in[0];
    const float* key   = (const float*)d_in[1];
    const float* value = (const float*)d_in[2];
    const int*   mask  = (const int*)d_in[3];
    const float* Wq = (const float*)d_in[4];
    const float* bq = (const float*)d_in[5];
    const float* Wk = (const float*)d_in[6];
    const float* bk = (const float*)d_in[7];
    const float* Wv = (const float*)d_in[8];
    const float* bv = (const float*)d_in[9];
    const float* Wo = (const float*)d_in[10];
    const float* bo = (const float*)d_in[11];
    float* out = (float*)d_out;

    void *pQ, *pK, *pV, *pC;
    cudaGetSymbolAddress(&pQ, g_Q);
    cudaGetSymbolAddress(&pK, g_K);
    cudaGetSymbolAddress(&pV, g_V);
    cudaGetSymbolAddress(&pC, g_CTX);

    static int smem_set = 0;
    const int fsmem = FSMEM_FLOATS * (int)sizeof(float);
    if (!smem_set) {
        cudaFuncSetAttribute(flash_attn_mma, cudaFuncAttributeMaxDynamicSharedMemorySize, fsmem);
        smem_set = 1;
    }

    dim3 gridP(D_MODEL / GBN, S_LEN / GBM);   // (12, 64)
    const float qscale = 1.0f / 8.0f;         // 1/sqrt(64)

    gemm_tf32<<<gridP, 128>>>(query, Wq, bq, (float*)pQ, S_LEN, D_MODEL, D_MODEL, qscale);
    gemm_tf32<<<gridP, 128>>>(key,   Wk, bk, (float*)pK, S_LEN, D_MODEL, D_MODEL, 1.0f);
    gemm_tf32<<<gridP, 128>>>(value, Wv, bv, (float*)pV, S_LEN, D_MODEL, D_MODEL, 1.0f);

    dim3 gridA(S_LEN / FBQ, N_HEADS);         // (64, 12)
    flash_attn_mma<<<gridA, 128, fsmem>>>((const float*)pQ, (const float*)pK,
                                          (const float*)pV, mask, (float*)pC);

    gemm_tf32<<<gridP, 128>>>((const float*)pC, Wo, bo, out, S_LEN, D_MODEL, D_MODEL, 1.0f);
}